// round 3
// baseline (speedup 1.0000x reference)
#include <cuda_runtime.h>

#define NN 50000
#define EE 600000
#define PP 100000
#define FD 128

// ---- device scratch ----
__device__ float g_agg[NN * FD];
__device__ float g_deg[NN];
__device__ float g_h1[NN * FD];
__device__ float g_h2[NN * FD];

typedef unsigned long long u64;

__device__ __forceinline__ void ffma2(u64& d, u64 a, u64 b) {
    asm("fma.rn.f32x2 %0, %1, %2, %0;" : "+l"(d) : "l"(a), "l"(b));
}
__device__ __forceinline__ void unpack2(float& lo, float& hi, u64 v) {
    asm("mov.b64 {%0, %1}, %2;" : "=f"(lo), "=f"(hi) : "l"(v));
}
__device__ __forceinline__ u64 pack2(float lo, float hi) {
    u64 r;
    asm("mov.b64 %0, {%1, %2};" : "=l"(r) : "f"(lo), "f"(hi));
    return r;
}

// ============================================================================
// Scatter: one warp per edge, vector reduction
// ============================================================================
__global__ void scatter_kernel(const float* __restrict__ h,
                               const int* __restrict__ src,
                               const int* __restrict__ dst,
                               int addDeg)
{
    int gid  = blockIdx.x * blockDim.x + threadIdx.x;
    int e    = gid >> 5;
    int lane = gid & 31;
    if (e >= EE) return;
    int s = src[e];
    int d = dst[e];
    float4 v = *(const float4*)(h + s * FD + lane * 4);
    float* a = g_agg + d * FD + lane * 4;
    asm volatile("red.global.add.v4.f32 [%0], {%1, %2, %3, %4};"
                 :: "l"(a), "f"(v.x), "f"(v.y), "f"(v.z), "f"(v.w)
                 : "memory");
    if (addDeg && lane == 0)
        asm volatile("red.global.add.f32 [%0], %1;"
                     :: "l"(g_deg + d), "f"(1.0f) : "memory");
}

// ============================================================================
// SAGE linear, k-interleaved FFMA2, 8 rows x 64 cols per warp.
// Weights packed in smem as u64 pairs (W[2t][c], W[2t+1][c]).
// acc holds (sum over even k, sum over odd k); collapsed at epilogue.
// ============================================================================
template <bool RELU>
__global__ void __launch_bounds__(512, 1)
sage_linear_kernel(const float* __restrict__ x,
                   const float* __restrict__ Ws,
                   const float* __restrict__ Wn,
                   const float* __restrict__ b,
                   float* __restrict__ out)
{
    extern __shared__ float sm[];
    u64*   smWp  = (u64*)sm;            // [128 pairs][128 cols]  (128 KB)
    float* stage = sm + 2 * 128 * 128;  // [8 rowgroups][8 rows][256]  (64 KB)

    int tid  = threadIdx.x;
    int lane = tid & 31;
    int warp = tid >> 5;
    int rg   = warp >> 1;    // rowgroup 0..7
    int half = warp & 1;     // column half 0..1

    // build k-interleaved packed weights: smWp[t*128+c] = (W[2t][c], W[2t+1][c])
    for (int i = tid; i < 128 * 128; i += blockDim.x) {
        int t = i >> 7, c = i & 127;
        int k0 = 2 * t;
        float w0, w1;
        if (k0 < 128) { w0 = Ws[k0 * 128 + c];         w1 = Ws[(k0 + 1) * 128 + c]; }
        else          { w0 = Wn[(k0 - 128) * 128 + c]; w1 = Wn[(k0 - 127) * 128 + c]; }
        smWp[i] = pack2(w0, w1);
    }
    __syncthreads();

    int c0 = half * 64 + lane * 2;
    const float2 bias = *(const float2*)(b + c0);
    float* srow_base = stage + rg * (8 * 256);
    const u64* wcol = smWp + c0;

    for (int base = blockIdx.x * 64; base < NN; base += gridDim.x * 64) {
        // ---- stage: each warp stages 4 of its rowgroup's 8 rows ----
#pragma unroll
        for (int r = 0; r < 4; r++) {
            int lr  = half * 4 + r;
            int row = base + rg * 8 + lr;
            float4 xv = make_float4(0.f, 0.f, 0.f, 0.f);
            float4 mv = make_float4(0.f, 0.f, 0.f, 0.f);
            if (row < NN) {
                xv = *(const float4*)(x + row * FD + lane * 4);
                float4 av = *(const float4*)(g_agg + row * FD + lane * 4);
                float rd = 1.0f / fmaxf(g_deg[row], 1.0f);
                mv.x = av.x * rd; mv.y = av.y * rd;
                mv.z = av.z * rd; mv.w = av.w * rd;
            }
            *(float4*)(srow_base + lr * 256 + lane * 4)       = xv;
            *(float4*)(srow_base + lr * 256 + 128 + lane * 4) = mv;
        }
        __syncthreads();

        u64 acc[8][2];
#pragma unroll
        for (int r = 0; r < 8; r++) { acc[r][0] = 0ull; acc[r][1] = 0ull; }

        // k pairs t=0..127; 2 pairs (4 k) per step
#pragma unroll 4
        for (int t = 0; t < 128; t += 2) {
            ulonglong2 w0 = *(const ulonglong2*)(wcol + t * 128);        // pair t,   cols c0,c0+1
            ulonglong2 w1 = *(const ulonglong2*)(wcol + (t + 1) * 128);  // pair t+1, cols c0,c0+1
#pragma unroll
            for (int r = 0; r < 8; r++) {
                ulonglong2 a = *(const ulonglong2*)(srow_base + r * 256 + t * 2);
                ffma2(acc[r][0], a.x, w0.x);
                ffma2(acc[r][1], a.x, w0.y);
                ffma2(acc[r][0], a.y, w1.x);
                ffma2(acc[r][1], a.y, w1.y);
            }
        }

#pragma unroll
        for (int r = 0; r < 8; r++) {
            int row = base + rg * 8 + r;
            if (row < NN) {
                float lo0, hi0, lo1, hi1;
                unpack2(lo0, hi0, acc[r][0]);
                unpack2(lo1, hi1, acc[r][1]);
                float2 o;
                o.x = lo0 + hi0 + bias.x;
                o.y = lo1 + hi1 + bias.y;
                if (RELU) { o.x = fmaxf(o.x, 0.f); o.y = fmaxf(o.y, 0.f); }
                *(float2*)(out + row * FD + c0) = o;
            }
        }
        __syncthreads();
    }
}

// ============================================================================
// Fused decoder, same 8x64 warp tiling + k-interleaved FFMA2.
// ============================================================================
__global__ void __launch_bounds__(512, 1)
decoder_kernel(const float* __restrict__ h,
               const int* __restrict__ ps, const int* __restrict__ pd,
               const int* __restrict__ ns, const int* __restrict__ nd,
               const float* __restrict__ Wd1, const float* __restrict__ bd1,
               const float* __restrict__ Wd2, const float* __restrict__ bd2,
               const float* __restrict__ Wd3, const float* __restrict__ bd3,
               float* __restrict__ out)
{
    extern __shared__ float sm[];
    u64*   smW1p = (u64*)sm;             // [64 pairs][128 cols] (64 KB)
    u64*   smW2p = (u64*)sm + 64 * 128;  // [64 pairs][128 cols] (64 KB)
    float* stage = sm + 4 * 64 * 128;    // [8 rg][8 rows][128]  (32 KB)
    float* hd    = stage + 8 * 8 * 128;  // half-dots [64][2]    (512 B)

    int tid  = threadIdx.x;
    int lane = tid & 31;
    int warp = tid >> 5;
    int rg   = warp >> 1;
    int half = warp & 1;

    for (int i = tid; i < 64 * 128; i += blockDim.x) {
        int t = i >> 7, c = i & 127;
        smW1p[i] = pack2(Wd1[2 * t * 128 + c], Wd1[(2 * t + 1) * 128 + c]);
        smW2p[i] = pack2(Wd2[2 * t * 128 + c], Wd2[(2 * t + 1) * 128 + c]);
    }
    __syncthreads();

    int c0 = half * 64 + lane * 2;
    const float2 b1v = *(const float2*)(bd1 + c0);
    const float2 b2v = *(const float2*)(bd2 + c0);
    const float2 w3v = *(const float2*)(Wd3 + c0);
    const float  b3  = bd3[0];

    float* srow_base = stage + rg * (8 * 128);
    const u64* w1col = smW1p + c0;
    const u64* w2col = smW2p + c0;
    const int total = 2 * PP;

    for (int base = blockIdx.x * 64; base < total; base += gridDim.x * 64) {
        // ---- stage z = h[s]*h[d]: each warp stages 4 of its rg's rows ----
#pragma unroll
        for (int r = 0; r < 4; r++) {
            int lr = half * 4 + r;
            int p  = base + rg * 8 + lr;
            float4 z = make_float4(0.f, 0.f, 0.f, 0.f);
            if (p < total) {
                int s, d;
                if (p < PP) { s = ps[p]; d = pd[p]; }
                else        { s = ns[p - PP]; d = nd[p - PP]; }
                float4 a = *(const float4*)(h + s * FD + lane * 4);
                float4 c4 = *(const float4*)(h + d * FD + lane * 4);
                z.x = a.x * c4.x; z.y = a.y * c4.y;
                z.z = a.z * c4.z; z.w = a.w * c4.w;
            }
            *(float4*)(srow_base + lr * 128 + lane * 4) = z;
        }
        __syncthreads();

        u64 acc[8][2];

        // ---- GEMV 1 ----
#pragma unroll
        for (int r = 0; r < 8; r++) { acc[r][0] = 0ull; acc[r][1] = 0ull; }
#pragma unroll 4
        for (int t = 0; t < 64; t += 2) {
            ulonglong2 w0 = *(const ulonglong2*)(w1col + t * 128);
            ulonglong2 w1 = *(const ulonglong2*)(w1col + (t + 1) * 128);
#pragma unroll
            for (int r = 0; r < 8; r++) {
                ulonglong2 a = *(const ulonglong2*)(srow_base + r * 128 + t * 2);
                ffma2(acc[r][0], a.x, w0.x);
                ffma2(acc[r][1], a.x, w0.y);
                ffma2(acc[r][0], a.y, w1.x);
                ffma2(acc[r][1], a.y, w1.y);
            }
        }
        __syncthreads();   // all reads of stage done before t1 overwrite

        // t1 = relu(.) -> restage (each warp writes its 2 cols of its 8 rows)
#pragma unroll
        for (int r = 0; r < 8; r++) {
            float lo0, hi0, lo1, hi1;
            unpack2(lo0, hi0, acc[r][0]);
            unpack2(lo1, hi1, acc[r][1]);
            float2 t;
            t.x = fmaxf(lo0 + hi0 + b1v.x, 0.f);
            t.y = fmaxf(lo1 + hi1 + b1v.y, 0.f);
            *(float2*)(srow_base + r * 128 + c0) = t;
        }
        __syncthreads();

        // ---- GEMV 2 ----
#pragma unroll
        for (int r = 0; r < 8; r++) { acc[r][0] = 0ull; acc[r][1] = 0ull; }
#pragma unroll 4
        for (int t = 0; t < 64; t += 2) {
            ulonglong2 w0 = *(const ulonglong2*)(w2col + t * 128);
            ulonglong2 w1 = *(const ulonglong2*)(w2col + (t + 1) * 128);
#pragma unroll
            for (int r = 0; r < 8; r++) {
                ulonglong2 a = *(const ulonglong2*)(srow_base + r * 128 + t * 2);
                ffma2(acc[r][0], a.x, w0.x);
                ffma2(acc[r][1], a.x, w0.y);
                ffma2(acc[r][0], a.y, w1.x);
                ffma2(acc[r][1], a.y, w1.y);
            }
        }

        // ---- t2 = relu(.+b2); half-dot with Wd3, warp reduce, exchange ----
#pragma unroll
        for (int r = 0; r < 8; r++) {
            float lo0, hi0, lo1, hi1;
            unpack2(lo0, hi0, acc[r][0]);
            unpack2(lo1, hi1, acc[r][1]);
            float t0 = fmaxf(lo0 + hi0 + b2v.x, 0.f);
            float t1 = fmaxf(lo1 + hi1 + b2v.y, 0.f);
            float partial = t0 * w3v.x + t1 * w3v.y;
#pragma unroll
            for (int off = 16; off > 0; off >>= 1)
                partial += __shfl_xor_sync(0xffffffffu, partial, off);
            if (lane == 0) hd[(rg * 8 + r) * 2 + half] = partial;
        }
        __syncthreads();

        if (tid < 64) {
            int p = base + tid;
            if (p < total) out[p] = hd[tid * 2] + hd[tid * 2 + 1] + b3;
        }
        __syncthreads();
    }
}

// ============================================================================
// launch
// ============================================================================
extern "C" void kernel_launch(void* const* d_in, const int* in_sizes, int n_in,
                              void* d_out, int out_size)
{
    const float* x    = (const float*)d_in[0];
    const int*   esrc = (const int*)  d_in[1];
    const int*   edst = (const int*)  d_in[2];
    const int*   ps   = (const int*)  d_in[3];
    const int*   pd   = (const int*)  d_in[4];
    const int*   ns   = (const int*)  d_in[5];
    const int*   nd   = (const int*)  d_in[6];
    const float* Ws1  = (const float*)d_in[7];
    const float* Wn1  = (const float*)d_in[8];
    const float* b1   = (const float*)d_in[9];
    const float* Ws2  = (const float*)d_in[10];
    const float* Wn2  = (const float*)d_in[11];
    const float* b2   = (const float*)d_in[12];
    const float* Wd1  = (const float*)d_in[13];
    const float* bd1  = (const float*)d_in[14];
    const float* Wd2  = (const float*)d_in[15];
    const float* bd2  = (const float*)d_in[16];
    const float* Wd3  = (const float*)d_in[17];
    const float* bd3  = (const float*)d_in[18];
    float* out = (float*)d_out;

    void *aggPtr, *degPtr, *h1Ptr, *h2Ptr;
    cudaGetSymbolAddress(&aggPtr, g_agg);
    cudaGetSymbolAddress(&degPtr, g_deg);
    cudaGetSymbolAddress(&h1Ptr,  g_h1);
    cudaGetSymbolAddress(&h2Ptr,  g_h2);

    int nsm = 148;
    cudaDeviceGetAttribute(&nsm, cudaDevAttrMultiProcessorCount, 0);

    const int SAGE_SMEM = 2 * 128 * 128 * 4 + 8 * 8 * 256 * 4;            // 196608 B
    const int DEC_SMEM  = 2 * 64 * 128 * 8 + 8 * 8 * 128 * 4 + 64 * 2 * 4; // 164352 B
    cudaFuncSetAttribute(sage_linear_kernel<true>,
                         cudaFuncAttributeMaxDynamicSharedMemorySize, SAGE_SMEM);
    cudaFuncSetAttribute(sage_linear_kernel<false>,
                         cudaFuncAttributeMaxDynamicSharedMemorySize, SAGE_SMEM);
    cudaFuncSetAttribute(decoder_kernel,
                         cudaFuncAttributeMaxDynamicSharedMemorySize, DEC_SMEM);

    int sblocks = (EE * 32 + 255) / 256;

    // ---- layer 1 ----
    cudaMemsetAsync(aggPtr, 0, sizeof(float) * NN * FD, 0);
    cudaMemsetAsync(degPtr, 0, sizeof(float) * NN, 0);
    scatter_kernel<<<sblocks, 256>>>(x, esrc, edst, 1);
    sage_linear_kernel<true><<<nsm, 512, SAGE_SMEM>>>(x, Ws1, Wn1, b1,
                                                      (float*)h1Ptr);
    // ---- layer 2 ----
    cudaMemsetAsync(aggPtr, 0, sizeof(float) * NN * FD, 0);
    scatter_kernel<<<sblocks, 256>>>((const float*)h1Ptr, esrc, edst, 0);
    sage_linear_kernel<false><<<nsm, 512, SAGE_SMEM>>>((const float*)h1Ptr,
                                                       Ws2, Wn2, b2,
                                                       (float*)h2Ptr);
    // ---- decoder ----
    decoder_kernel<<<nsm, 512, DEC_SMEM>>>((const float*)h2Ptr,
                                           ps, pd, ns, nd,
                                           Wd1, bd1, Wd2, bd2, Wd3, bd3, out);
}

// round 5
// speedup vs baseline: 1.3825x; 1.3825x over previous
#include <cuda_runtime.h>
#include <cstdint>

#define NN 50000
#define EE 600000
#define PP 100000
#define FD 128

// ---- device scratch ----
__device__ float g_agg[NN * FD];     // holds MEAN aggregate (division folded in)
__device__ float g_h1[NN * FD];
__device__ float g_h2[NN * FD];
__device__ int   g_cnt[NN];
__device__ int   g_cur[NN];
__device__ int   g_rowstart[NN + 1];
__device__ int   g_csr[EE];

typedef unsigned long long u64;

__device__ __forceinline__ void ffma2(u64& d, u64 a, u64 b) {
    asm("fma.rn.f32x2 %0, %1, %2, %0;" : "+l"(d) : "l"(a), "l"(b));
}
__device__ __forceinline__ void unpack2(float& lo, float& hi, u64 v) {
    asm("mov.b64 {%0, %1}, %2;" : "=f"(lo), "=f"(hi) : "l"(v));
}
__device__ __forceinline__ u64 pack_dup(float a) {
    u64 r;
    asm("mov.b64 %0, {%1, %1};" : "=l"(r) : "f"(a));
    return r;
}

// ============================================================================
// CSR build: count -> scan -> fill   (once per launch, reused by both layers)
// ============================================================================
__global__ void count_kernel(const int* __restrict__ dst)
{
    int e = blockIdx.x * blockDim.x + threadIdx.x;
    if (e < EE) atomicAdd(&g_cnt[dst[e]], 1);
}

__global__ void __launch_bounds__(1024, 1) scan_kernel()
{
    __shared__ int wsum[32];
    __shared__ int carry;
    int tid = threadIdx.x, lane = tid & 31, w = tid >> 5;
    if (tid == 0) carry = 0;
    __syncthreads();
    for (int base = 0; base < NN; base += 1024) {
        int i = base + tid;
        int v = (i < NN) ? g_cnt[i] : 0;
        int s = v;
#pragma unroll
        for (int off = 1; off < 32; off <<= 1) {
            int t = __shfl_up_sync(0xffffffffu, s, off);
            if (lane >= off) s += t;
        }
        if (lane == 31) wsum[w] = s;
        __syncthreads();
        if (w == 0) {
            int ws = wsum[lane];
#pragma unroll
            for (int off = 1; off < 32; off <<= 1) {
                int t = __shfl_up_sync(0xffffffffu, ws, off);
                if (lane >= off) ws += t;
            }
            wsum[lane] = ws;
        }
        __syncthreads();
        int prev = (w > 0) ? wsum[w - 1] : 0;
        int incl = carry + prev + s;
        if (i < NN) g_rowstart[i + 1] = incl;
        int chunk_total = wsum[31];
        __syncthreads();
        if (tid == 0) carry += chunk_total;
        __syncthreads();
    }
    if (threadIdx.x == 0) g_rowstart[0] = 0;
}

__global__ void fill_kernel(const int* __restrict__ src,
                            const int* __restrict__ dst)
{
    int e = blockIdx.x * blockDim.x + threadIdx.x;
    if (e >= EE) return;
    int d = dst[e];
    int p = atomicAdd(&g_cur[d], 1);
    g_csr[g_rowstart[d] + p] = src[e];
}

// ============================================================================
// Aggregate: one warp per node, gather + accumulate, write MEAN. No atomics.
// ============================================================================
__global__ void aggregate_kernel(const float* __restrict__ h)
{
    int gw   = (blockIdx.x * blockDim.x + threadIdx.x) >> 5;
    int lane = threadIdx.x & 31;
    if (gw >= NN) return;
    int beg = g_rowstart[gw], end = g_rowstart[gw + 1];
    const float* hp = h + lane * 4;
    float4 acc = make_float4(0.f, 0.f, 0.f, 0.f);
    int e = beg;
    for (; e + 1 < end; e += 2) {          // 2-way unroll for MLP
        int s0 = g_csr[e], s1 = g_csr[e + 1];
        float4 v0 = *(const float4*)(hp + s0 * FD);
        float4 v1 = *(const float4*)(hp + s1 * FD);
        acc.x += v0.x + v1.x; acc.y += v0.y + v1.y;
        acc.z += v0.z + v1.z; acc.w += v0.w + v1.w;
    }
    if (e < end) {
        int s0 = g_csr[e];
        float4 v0 = *(const float4*)(hp + s0 * FD);
        acc.x += v0.x; acc.y += v0.y; acc.z += v0.z; acc.w += v0.w;
    }
    float rd = 1.0f / fmaxf((float)(end - beg), 1.0f);
    acc.x *= rd; acc.y *= rd; acc.z *= rd; acc.w *= rd;
    *(float4*)(g_agg + gw * FD + lane * 4) = acc;
}

// ============================================================================
// SAGE linear: FFMA2, 8 rows x 128 cols per warp, K staged in two halves.
// smem: weights [256][128] fp32 (128KB) + stage [16 warps][8 rows][128] (64KB)
// ============================================================================
template <bool RELU>
__global__ void __launch_bounds__(512, 1)
sage_linear_kernel(const float* __restrict__ x,
                   const float* __restrict__ Ws,
                   const float* __restrict__ Wn,
                   const float* __restrict__ b,
                   float* __restrict__ out)
{
    extern __shared__ float sm[];
    float* smW   = sm;                 // [256][128]
    float* stage = sm + 256 * 128;     // [16][8][128]

    int tid  = threadIdx.x;
    int lane = tid & 31;
    int warp = tid >> 5;

    for (int i = tid; i < (128 * 128) / 4; i += blockDim.x) {
        ((float4*)smW)[i]               = ((const float4*)Ws)[i];
        ((float4*)(smW + 128 * 128))[i] = ((const float4*)Wn)[i];
    }
    __syncthreads();

    float4 bias = *(const float4*)(b + lane * 4);
    float* myStage = stage + warp * (8 * 128);

    for (int base = blockIdx.x * 128 + warp * 8; base < NN;
         base += gridDim.x * 128) {

        u64 acc[8][2];
#pragma unroll
        for (int r = 0; r < 8; r++) { acc[r][0] = 0ull; acc[r][1] = 0ull; }

#pragma unroll 1
        for (int h = 0; h < 2; h++) {
            // ---- stage 8 rows of this K-half (warp-local) ----
#pragma unroll
            for (int r = 0; r < 8; r++) {
                int row = base + r;
                float4 v = make_float4(0.f, 0.f, 0.f, 0.f);
                if (row < NN) {
                    const float* p = (h == 0) ? x : (const float*)g_agg;
                    v = *(const float4*)(p + row * FD + lane * 4);
                }
                *(float4*)(myStage + r * 128 + lane * 4) = v;
            }
            __syncwarp();

            const float* wbase = smW + h * 128 * 128;
#pragma unroll 1
            for (int k = 0; k < 128; k += 4) {
                float4 xq[8];
#pragma unroll
                for (int r = 0; r < 8; r++)
                    xq[r] = *(const float4*)(myStage + r * 128 + k);
#pragma unroll
                for (int kk = 0; kk < 4; kk++) {
                    ulonglong2 w = *(const ulonglong2*)(wbase + (k + kk) * 128 + lane * 4);
#pragma unroll
                    for (int r = 0; r < 8; r++) {
                        float xs = (kk == 0) ? xq[r].x : (kk == 1) ? xq[r].y
                                 : (kk == 2) ? xq[r].z : xq[r].w;
                        u64 xx = pack_dup(xs);
                        ffma2(acc[r][0], xx, w.x);
                        ffma2(acc[r][1], xx, w.y);
                    }
                }
            }
            __syncwarp();
        }

#pragma unroll
        for (int r = 0; r < 8; r++) {
            int row = base + r;
            if (row < NN) {
                float4 o;
                unpack2(o.x, o.y, acc[r][0]);
                unpack2(o.z, o.w, acc[r][1]);
                o.x += bias.x; o.y += bias.y; o.z += bias.z; o.w += bias.w;
                if (RELU) {
                    o.x = fmaxf(o.x, 0.f); o.y = fmaxf(o.y, 0.f);
                    o.z = fmaxf(o.z, 0.f); o.w = fmaxf(o.w, 0.f);
                }
                *(float4*)(out + row * FD + lane * 4) = o;
            }
        }
    }
}

// ============================================================================
// Fused decoder: FFMA2, 8 rows x 128 cols per warp.
// smem: W1 (64KB) + W2 (64KB) + stage [16][8][128] (64KB)
// ============================================================================
__global__ void __launch_bounds__(512, 1)
decoder_kernel(const float* __restrict__ h,
               const int* __restrict__ ps, const int* __restrict__ pd,
               const int* __restrict__ ns, const int* __restrict__ nd,
               const float* __restrict__ Wd1, const float* __restrict__ bd1,
               const float* __restrict__ Wd2, const float* __restrict__ bd2,
               const float* __restrict__ Wd3, const float* __restrict__ bd3,
               float* __restrict__ out)
{
    extern __shared__ float sm[];
    float* smW1  = sm;                 // [128][128]
    float* smW2  = sm + 128 * 128;     // [128][128]
    float* stage = sm + 2 * 128 * 128; // [16][8][128]

    int tid  = threadIdx.x;
    int lane = tid & 31;
    int warp = tid >> 5;

    for (int i = tid; i < (128 * 128) / 4; i += blockDim.x) {
        ((float4*)smW1)[i] = ((const float4*)Wd1)[i];
        ((float4*)smW2)[i] = ((const float4*)Wd2)[i];
    }
    __syncthreads();

    float4 b1v = *(const float4*)(bd1 + lane * 4);
    float4 b2v = *(const float4*)(bd2 + lane * 4);
    float4 w3v = *(const float4*)(Wd3 + lane * 4);
    float  b3  = bd3[0];

    float* myStage = stage + warp * (8 * 128);
    const int total = 2 * PP;

    for (int base = blockIdx.x * 128 + warp * 8; base < total;
         base += gridDim.x * 128) {
        // ---- stage z = h[s] * h[d] ----
#pragma unroll
        for (int r = 0; r < 8; r++) {
            int p = base + r;
            float4 z = make_float4(0.f, 0.f, 0.f, 0.f);
            if (p < total) {
                int s, d;
                if (p < PP) { s = ps[p]; d = pd[p]; }
                else        { s = ns[p - PP]; d = nd[p - PP]; }
                float4 a = *(const float4*)(h + s * FD + lane * 4);
                float4 c = *(const float4*)(h + d * FD + lane * 4);
                z.x = a.x * c.x; z.y = a.y * c.y;
                z.z = a.z * c.z; z.w = a.w * c.w;
            }
            *(float4*)(myStage + r * 128 + lane * 4) = z;
        }
        __syncwarp();

        u64 acc[8][2];

        // ---- GEMV 1 ----
#pragma unroll
        for (int r = 0; r < 8; r++) { acc[r][0] = 0ull; acc[r][1] = 0ull; }
#pragma unroll 1
        for (int k = 0; k < 128; k += 4) {
            float4 zq[8];
#pragma unroll
            for (int r = 0; r < 8; r++)
                zq[r] = *(const float4*)(myStage + r * 128 + k);
#pragma unroll
            for (int kk = 0; kk < 4; kk++) {
                ulonglong2 w = *(const ulonglong2*)(smW1 + (k + kk) * 128 + lane * 4);
#pragma unroll
                for (int r = 0; r < 8; r++) {
                    float zs = (kk == 0) ? zq[r].x : (kk == 1) ? zq[r].y
                             : (kk == 2) ? zq[r].z : zq[r].w;
                    u64 zz = pack_dup(zs);
                    ffma2(acc[r][0], zz, w.x);
                    ffma2(acc[r][1], zz, w.y);
                }
            }
        }
        __syncwarp();

        // ---- t1 = relu(acc + b1) -> restage (warp-local) ----
#pragma unroll
        for (int r = 0; r < 8; r++) {
            float lo0, hi0, lo1, hi1;
            unpack2(lo0, hi0, acc[r][0]);
            unpack2(lo1, hi1, acc[r][1]);
            float4 tq;
            tq.x = fmaxf(lo0 + b1v.x, 0.f);
            tq.y = fmaxf(hi0 + b1v.y, 0.f);
            tq.z = fmaxf(lo1 + b1v.z, 0.f);
            tq.w = fmaxf(hi1 + b1v.w, 0.f);
            *(float4*)(myStage + r * 128 + lane * 4) = tq;
        }
        __syncwarp();

        // ---- GEMV 2 ----
#pragma unroll
        for (int r = 0; r < 8; r++) { acc[r][0] = 0ull; acc[r][1] = 0ull; }
#pragma unroll 1
        for (int k = 0; k < 128; k += 4) {
            float4 zq[8];
#pragma unroll
            for (int r = 0; r < 8; r++)
                zq[r] = *(const float4*)(myStage + r * 128 + k);
#pragma unroll
            for (int kk = 0; kk < 4; kk++) {
                ulonglong2 w = *(const ulonglong2*)(smW2 + (k + kk) * 128 + lane * 4);
#pragma unroll
                for (int r = 0; r < 8; r++) {
                    float zs = (kk == 0) ? zq[r].x : (kk == 1) ? zq[r].y
                             : (kk == 2) ? zq[r].z : zq[r].w;
                    u64 zz = pack_dup(zs);
                    ffma2(acc[r][0], zz, w.x);
                    ffma2(acc[r][1], zz, w.y);
                }
            }
        }

        // ---- out = relu(acc + b2) . Wd3 + bd3 ----
#pragma unroll
        for (int r = 0; r < 8; r++) {
            float t0, t1, t2, t3;
            unpack2(t0, t1, acc[r][0]);
            unpack2(t2, t3, acc[r][1]);
            t0 = fmaxf(t0 + b2v.x, 0.f);
            t1 = fmaxf(t1 + b2v.y, 0.f);
            t2 = fmaxf(t2 + b2v.z, 0.f);
            t3 = fmaxf(t3 + b2v.w, 0.f);
            float partial = t0 * w3v.x + t1 * w3v.y + t2 * w3v.z + t3 * w3v.w;
#pragma unroll
            for (int off = 16; off > 0; off >>= 1)
                partial += __shfl_xor_sync(0xffffffffu, partial, off);
            int p = base + r;
            if (lane == 0 && p < total) out[p] = partial + b3;
        }
        __syncwarp();
    }
}

// ============================================================================
// launch
// ============================================================================
extern "C" void kernel_launch(void* const* d_in, const int* in_sizes, int n_in,
                              void* d_out, int out_size)
{
    const float* x    = (const float*)d_in[0];
    const int*   esrc = (const int*)  d_in[1];
    const int*   edst = (const int*)  d_in[2];
    const int*   ps   = (const int*)  d_in[3];
    const int*   pd   = (const int*)  d_in[4];
    const int*   ns   = (const int*)  d_in[5];
    const int*   nd   = (const int*)  d_in[6];
    const float* Ws1  = (const float*)d_in[7];
    const float* Wn1  = (const float*)d_in[8];
    const float* b1   = (const float*)d_in[9];
    const float* Ws2  = (const float*)d_in[10];
    const float* Wn2  = (const float*)d_in[11];
    const float* b2   = (const float*)d_in[12];
    const float* Wd1  = (const float*)d_in[13];
    const float* bd1  = (const float*)d_in[14];
    const float* Wd2  = (const float*)d_in[15];
    const float* bd2  = (const float*)d_in[16];
    const float* Wd3  = (const float*)d_in[17];
    const float* bd3  = (const float*)d_in[18];
    float* out = (float*)d_out;

    void *cntPtr, *curPtr, *h1Ptr, *h2Ptr;
    cudaGetSymbolAddress(&cntPtr, g_cnt);
    cudaGetSymbolAddress(&curPtr, g_cur);
    cudaGetSymbolAddress(&h1Ptr,  g_h1);
    cudaGetSymbolAddress(&h2Ptr,  g_h2);

    int nsm = 148;
    cudaDeviceGetAttribute(&nsm, cudaDevAttrMultiProcessorCount, 0);

    const int SAGE_SMEM = 256 * 128 * 4 + 16 * 8 * 128 * 4;       // 196608 B
    const int DEC_SMEM  = 2 * 128 * 128 * 4 + 16 * 8 * 128 * 4;   // 196608 B
    cudaFuncSetAttribute(sage_linear_kernel<true>,
                         cudaFuncAttributeMaxDynamicSharedMemorySize, SAGE_SMEM);
    cudaFuncSetAttribute(sage_linear_kernel<false>,
                         cudaFuncAttributeMaxDynamicSharedMemorySize, SAGE_SMEM);
    cudaFuncSetAttribute(decoder_kernel,
                         cudaFuncAttributeMaxDynamicSharedMemorySize, DEC_SMEM);

    // ---- CSR build (once; reused by both layers) ----
    cudaMemsetAsync(cntPtr, 0, sizeof(int) * NN, 0);
    cudaMemsetAsync(curPtr, 0, sizeof(int) * NN, 0);
    count_kernel<<<(EE + 255) / 256, 256>>>(edst);
    scan_kernel<<<1, 1024>>>();
    fill_kernel<<<(EE + 255) / 256, 256>>>(esrc, edst);

    int ablocks = (NN * 32 + 255) / 256;

    // ---- layer 1 ----
    aggregate_kernel<<<ablocks, 256>>>(x);
    sage_linear_kernel<true><<<nsm, 512, SAGE_SMEM>>>(x, Ws1, Wn1, b1,
                                                      (float*)h1Ptr);
    // ---- layer 2 ----
    aggregate_kernel<<<ablocks, 256>>>((const float*)h1Ptr);
    sage_linear_kernel<false><<<nsm, 512, SAGE_SMEM>>>((const float*)h1Ptr,
                                                       Ws2, Wn2, b2,
                                                       (float*)h2Ptr);
    // ---- decoder ----
    decoder_kernel<<<nsm, 512, DEC_SMEM>>>((const float*)h2Ptr,
                                           ps, pd, ns, nd,
                                           Wd1, bd1, Wd2, bd2, Wd3, bd3, out);
}